// round 3
// baseline (speedup 1.0000x reference)
#include <cuda_runtime.h>
#include <cuda_bf16.h>

#define BATCH 2
#define CH    256
#define NTOK  4096
#define NHEAD 8
#define DHEAD 64
#define INNER 512

// Scratch (no cudaMalloc allowed): q/k/v in [b][h][n][d], attn out in [b][i=h*64+d][n]
__device__ float g_q[BATCH*NHEAD*NTOK*DHEAD];
__device__ float g_k[BATCH*NHEAD*NTOK*DHEAD];
__device__ float g_v[BATCH*NHEAD*NTOK*DHEAD];
__device__ float g_o[BATCH*INNER*NTOK];

// ---------------------------------------------------------------------------
// Kernel 1: QKV projection.  Y[b,o,n] = sum_c W[o,c] * x[b,c,n]
// Tile 64(o) x 64(n), BK=16, 256 threads, 4x4 microtile.
// o0 is a multiple of 64 => (s, h) fixed per tile, row index within tile == d.
// Q is pre-scaled by 1/sqrt(DHEAD) = 0.125.
// ---------------------------------------------------------------------------
__global__ __launch_bounds__(256) void qkv_kernel(const float* __restrict__ x,
                                                  const float* __restrict__ w) {
    __shared__ float Ws[16][65];
    __shared__ float Xs[16][65];
    __shared__ float Ss[64][65];

    const int b  = blockIdx.z;
    const int o0 = blockIdx.y * 64;
    const int n0 = blockIdx.x * 64;
    const int tid = threadIdx.x;
    const int tx = tid & 15, ty = tid >> 4;

    const float* xb = x + (size_t)b * CH * NTOK;
    float acc[4][4] = {};

    for (int kt = 0; kt < CH; kt += 16) {
#pragma unroll
        for (int t = 0; t < 4; t++) {
            int l = t * 256 + tid;
            int o = l >> 4, kk = l & 15;
            Ws[kk][o] = w[(o0 + o) * CH + kt + kk];
        }
#pragma unroll
        for (int t = 0; t < 4; t++) {
            int l = t * 256 + tid;
            int kk = l >> 6, n = l & 63;
            Xs[kk][n] = xb[(size_t)(kt + kk) * NTOK + n0 + n];
        }
        __syncthreads();
#pragma unroll
        for (int kk = 0; kk < 16; kk++) {
            float a[4], bb[4];
#pragma unroll
            for (int i = 0; i < 4; i++) a[i]  = Ws[kk][ty * 4 + i];
#pragma unroll
            for (int j = 0; j < 4; j++) bb[j] = Xs[kk][tx + 16 * j];
#pragma unroll
            for (int i = 0; i < 4; i++)
#pragma unroll
                for (int j = 0; j < 4; j++)
                    acc[i][j] = fmaf(a[i], bb[j], acc[i][j]);
        }
        __syncthreads();
    }

#pragma unroll
    for (int i = 0; i < 4; i++)
#pragma unroll
        for (int j = 0; j < 4; j++)
            Ss[ty * 4 + i][tx + 16 * j] = acc[i][j];
    __syncthreads();

    const int s = o0 >> 9;           // 0=q 1=k 2=v
    const int h = (o0 >> 6) & 7;
    float* dst = (s == 0 ? g_q : (s == 1 ? g_k : g_v)) +
                 (size_t)(b * NHEAD + h) * NTOK * DHEAD;
    const float scale = (s == 0) ? 0.125f : 1.0f;
    // write coalesced along d (contiguous): tile row index == d, col == n
#pragma unroll
    for (int t = 0; t < 16; t++) {
        int l = t * 256 + tid;
        int n = l >> 6, d = l & 63;
        dst[(size_t)(n0 + n) * DHEAD + d] = Ss[d][n] * scale;
    }
}

// ---------------------------------------------------------------------------
// Kernel 2: flash attention, fp32 streaming softmax.
// grid (NTOK/64, NHEAD, BATCH), 256 threads. 64-query tile, 64-key tiles.
// ---------------------------------------------------------------------------
#define ATTN_SMEM_FLOATS (4 * 64 * 65 + 128)

__global__ __launch_bounds__(256) void attn_kernel() {
    extern __shared__ float sm[];
    float (*Qs)[65] = (float(*)[65])sm;
    float (*Ks)[65] = (float(*)[65])(sm + 64 * 65);
    float (*Vs)[65] = (float(*)[65])(sm + 2 * 64 * 65);
    float (*Ps)[65] = (float(*)[65])(sm + 3 * 64 * 65);
    float* alphas = sm + 4 * 64 * 65;
    float* lsums  = alphas + 64;

    const int b = blockIdx.z, h = blockIdx.y;
    const int n0 = blockIdx.x * 64;
    const int bh = b * NHEAD + h;
    const float* q = g_q + (size_t)bh * NTOK * DHEAD;
    const float* k = g_k + (size_t)bh * NTOK * DHEAD;
    const float* v = g_v + (size_t)bh * NTOK * DHEAD;

    const int tid = threadIdx.x;
    const int tx = tid & 15, ty = tid >> 4;
    const int r0 = ty * 4;

    // load Q tile
#pragma unroll
    for (int t = 0; t < 16; t++) {
        int l = t * 256 + tid;
        int r = l >> 6, d = l & 63;
        Qs[r][d] = q[(size_t)(n0 + r) * DHEAD + d];
    }

    float o_acc[4][4] = {};
    float m = -1e30f, lsum = 0.0f;

    for (int j0 = 0; j0 < NTOK; j0 += 64) {
        __syncthreads();   // guard K/V/P reuse from previous iteration
#pragma unroll
        for (int t = 0; t < 16; t++) {
            int l = t * 256 + tid;
            int r = l >> 6, d = l & 63;
            Ks[r][d] = k[(size_t)(j0 + r) * DHEAD + d];
            Vs[r][d] = v[(size_t)(j0 + r) * DHEAD + d];
        }
        __syncthreads();

        // S = Q @ K^T  (scale already folded into Q)
        float s_acc[4][4] = {};
#pragma unroll 8
        for (int kk = 0; kk < 64; kk++) {
            float a[4], bb[4];
#pragma unroll
            for (int i = 0; i < 4; i++) a[i]  = Qs[r0 + i][kk];
#pragma unroll
            for (int j = 0; j < 4; j++) bb[j] = Ks[tx + 16 * j][kk];
#pragma unroll
            for (int i = 0; i < 4; i++)
#pragma unroll
                for (int j = 0; j < 4; j++)
                    s_acc[i][j] = fmaf(a[i], bb[j], s_acc[i][j]);
        }
#pragma unroll
        for (int i = 0; i < 4; i++)
#pragma unroll
            for (int j = 0; j < 4; j++)
                Ps[r0 + i][tx + 16 * j] = s_acc[i][j];
        __syncthreads();

        // per-row online softmax (thread tid owns row tid, tid < 64)
        if (tid < 64) {
            float mx = m;
#pragma unroll 8
            for (int c = 0; c < 64; c++) mx = fmaxf(mx, Ps[tid][c]);
            float alpha = __expf(m - mx);
            float sum = 0.0f;
#pragma unroll 8
            for (int c = 0; c < 64; c++) {
                float p = __expf(Ps[tid][c] - mx);
                Ps[tid][c] = p;
                sum += p;
            }
            m = mx;
            lsum = lsum * alpha + sum;
            alphas[tid] = alpha;
        }
        __syncthreads();

        // O = O*alpha + P @ V
#pragma unroll
        for (int i = 0; i < 4; i++) {
            float a_ = alphas[r0 + i];
#pragma unroll
            for (int j = 0; j < 4; j++) o_acc[i][j] *= a_;
        }
#pragma unroll 8
        for (int kk = 0; kk < 64; kk++) {
            float p[4], vv[4];
#pragma unroll
            for (int i = 0; i < 4; i++) p[i]  = Ps[r0 + i][kk];
#pragma unroll
            for (int j = 0; j < 4; j++) vv[j] = Vs[kk][tx + 16 * j];
#pragma unroll
            for (int i = 0; i < 4; i++)
#pragma unroll
                for (int j = 0; j < 4; j++)
                    o_acc[i][j] = fmaf(p[i], vv[j], o_acc[i][j]);
        }
    }

    __syncthreads();
    if (tid < 64) lsums[tid] = lsum;
    __syncthreads();
#pragma unroll
    for (int i = 0; i < 4; i++) {
        float inv = 1.0f / lsums[r0 + i];
#pragma unroll
        for (int j = 0; j < 4; j++) o_acc[i][j] *= inv;
    }

    // stage and write transposed: g_o[(bh*64 + d)*NTOK + n]
#pragma unroll
    for (int i = 0; i < 4; i++)
#pragma unroll
        for (int j = 0; j < 4; j++)
            Ps[r0 + i][tx + 16 * j] = o_acc[i][j];
    __syncthreads();
    float* dst = g_o + (size_t)(bh * DHEAD) * NTOK;
#pragma unroll
    for (int t = 0; t < 16; t++) {
        int l = t * 256 + tid;
        int d = l >> 6, r = l & 63;
        dst[(size_t)d * NTOK + n0 + r] = Ps[r][d];
    }
}

// ---------------------------------------------------------------------------
// Kernel 3: output projection. out[b,c,n] = sum_i Wo[c,i]*g_o[b,i,n] + bias[c]
// ---------------------------------------------------------------------------
__global__ __launch_bounds__(256) void proj_kernel(const float* __restrict__ wo,
                                                   const float* __restrict__ bias,
                                                   float* __restrict__ out) {
    __shared__ float Ws[16][65];
    __shared__ float Xs[16][65];
    __shared__ float Ss[64][65];

    const int b  = blockIdx.z;
    const int c0 = blockIdx.y * 64;
    const int n0 = blockIdx.x * 64;
    const int tid = threadIdx.x;
    const int tx = tid & 15, ty = tid >> 4;

    const float* gb = g_o + (size_t)b * INNER * NTOK;
    float acc[4][4] = {};

    for (int kt = 0; kt < INNER; kt += 16) {
#pragma unroll
        for (int t = 0; t < 4; t++) {
            int l = t * 256 + tid;
            int o = l >> 4, kk = l & 15;
            Ws[kk][o] = wo[(c0 + o) * INNER + kt + kk];
        }
#pragma unroll
        for (int t = 0; t < 4; t++) {
            int l = t * 256 + tid;
            int kk = l >> 6, n = l & 63;
            Xs[kk][n] = gb[(size_t)(kt + kk) * NTOK + n0 + n];
        }
        __syncthreads();
#pragma unroll
        for (int kk = 0; kk < 16; kk++) {
            float a[4], bb[4];
#pragma unroll
            for (int i = 0; i < 4; i++) a[i]  = Ws[kk][ty * 4 + i];
#pragma unroll
            for (int j = 0; j < 4; j++) bb[j] = Xs[kk][tx + 16 * j];
#pragma unroll
            for (int i = 0; i < 4; i++)
#pragma unroll
                for (int j = 0; j < 4; j++)
                    acc[i][j] = fmaf(a[i], bb[j], acc[i][j]);
        }
        __syncthreads();
    }

#pragma unroll
    for (int i = 0; i < 4; i++)
#pragma unroll
        for (int j = 0; j < 4; j++)
            Ss[ty * 4 + i][tx + 16 * j] = acc[i][j];
    __syncthreads();

    // write coalesced along n
#pragma unroll
    for (int t = 0; t < 16; t++) {
        int l = t * 256 + tid;
        int r = l >> 6, n = l & 63;
        out[(size_t)(b * CH + c0 + r) * NTOK + n0 + n] = Ss[r][n] + bias[c0 + r];
    }
}

// ---------------------------------------------------------------------------
extern "C" void kernel_launch(void* const* d_in, const int* in_sizes, int n_in,
                              void* d_out, int out_size) {
    const float* x    = nullptr;
    const float* wqkv = nullptr;
    const float* wout = nullptr;
    const float* bout = nullptr;
    for (int i = 0; i < n_in; i++) {
        int sz = in_sizes[i];
        const float* p = (const float*)d_in[i];
        if      (sz == BATCH * CH * NTOK) x    = p;   // 2,097,152
        else if (sz == 3 * INNER * CH)    wqkv = p;   //   393,216
        else if (sz == CH * INNER)        wout = p;   //   131,072
        else if (sz == CH)                bout = p;   //       256
    }
    float* out = (float*)d_out;

    qkv_kernel<<<dim3(NTOK / 64, (3 * INNER) / 64, BATCH), 256>>>(x, wqkv);

    const int attn_smem = ATTN_SMEM_FLOATS * (int)sizeof(float);  // 67,072 B
    cudaFuncSetAttribute(attn_kernel,
                         cudaFuncAttributeMaxDynamicSharedMemorySize, attn_smem);
    attn_kernel<<<dim3(NTOK / 64, NHEAD, BATCH), 256, attn_smem>>>();

    proj_kernel<<<dim3(NTOK / 64, CH / 64, BATCH), 256>>>(wout, bout, out);
}

// round 5
// speedup vs baseline: 2.3838x; 2.3838x over previous
#include <cuda_runtime.h>
#include <cuda_bf16.h>
#include <cstdint>

#define BATCH 2
#define CH    256
#define NTOK  4096
#define NHEAD 8
#define DHEAD 64
#define INNER 512

// Scratch (no cudaMalloc allowed): q/k/v in [b][h][n][d], attn out in [b][i=h*64+d][n]
__device__ float g_q[BATCH*NHEAD*NTOK*DHEAD];
__device__ float g_k[BATCH*NHEAD*NTOK*DHEAD];
__device__ float g_v[BATCH*NHEAD*NTOK*DHEAD];
__device__ float g_o[BATCH*INNER*NTOK];

// ---------------------------------------------------------------------------
// tf32 helpers
// ---------------------------------------------------------------------------
__device__ __forceinline__ uint32_t f2tf32(float x) {
    uint32_t u;
    asm("cvt.rna.tf32.f32 %0, %1;" : "=r"(u) : "f"(x));
    return u;
}
__device__ __forceinline__ float f2tf32f(float x) {
    return __uint_as_float(f2tf32(x));
}
__device__ __forceinline__ void mma_tf32(float* c, const uint32_t* a,
                                         uint32_t b0, uint32_t b1) {
    asm volatile(
        "mma.sync.aligned.m16n8k8.row.col.f32.tf32.tf32.f32 "
        "{%0,%1,%2,%3}, {%4,%5,%6,%7}, {%8,%9}, {%0,%1,%2,%3};"
        : "+f"(c[0]), "+f"(c[1]), "+f"(c[2]), "+f"(c[3])
        : "r"(a[0]), "r"(a[1]), "r"(a[2]), "r"(a[3]), "r"(b0), "r"(b1));
}

// ---------------------------------------------------------------------------
// Kernel 1: QKV projection.  Y[b,o,n] = sum_c W[o,c] * x[b,c,n]
// Q pre-scaled by 1/sqrt(DHEAD) = 0.125. Output layout [b,h][n][d].
// ---------------------------------------------------------------------------
__global__ __launch_bounds__(256) void qkv_kernel(const float* __restrict__ x,
                                                  const float* __restrict__ w) {
    __shared__ float Ws[16][65];
    __shared__ float Xs[16][65];
    __shared__ float Ss[64][65];

    const int b  = blockIdx.z;
    const int o0 = blockIdx.y * 64;
    const int n0 = blockIdx.x * 64;
    const int tid = threadIdx.x;
    const int tx = tid & 15, ty = tid >> 4;

    const float* xb = x + (size_t)b * CH * NTOK;
    float acc[4][4] = {};

    for (int kt = 0; kt < CH; kt += 16) {
#pragma unroll
        for (int t = 0; t < 4; t++) {
            int l = t * 256 + tid;
            int o = l >> 4, kk = l & 15;
            Ws[kk][o] = w[(o0 + o) * CH + kt + kk];
        }
#pragma unroll
        for (int t = 0; t < 4; t++) {
            int l = t * 256 + tid;
            int kk = l >> 6, n = l & 63;
            Xs[kk][n] = xb[(size_t)(kt + kk) * NTOK + n0 + n];
        }
        __syncthreads();
#pragma unroll
        for (int kk = 0; kk < 16; kk++) {
            float a[4], bb[4];
#pragma unroll
            for (int i = 0; i < 4; i++) a[i]  = Ws[kk][ty * 4 + i];
#pragma unroll
            for (int j = 0; j < 4; j++) bb[j] = Xs[kk][tx + 16 * j];
#pragma unroll
            for (int i = 0; i < 4; i++)
#pragma unroll
                for (int j = 0; j < 4; j++)
                    acc[i][j] = fmaf(a[i], bb[j], acc[i][j]);
        }
        __syncthreads();
    }

#pragma unroll
    for (int i = 0; i < 4; i++)
#pragma unroll
        for (int j = 0; j < 4; j++)
            Ss[ty * 4 + i][tx + 16 * j] = acc[i][j];
    __syncthreads();

    const int s = o0 >> 9;           // 0=q 1=k 2=v
    const int h = (o0 >> 6) & 7;
    float* dst = (s == 0 ? g_q : (s == 1 ? g_k : g_v)) +
                 (size_t)(b * NHEAD + h) * NTOK * DHEAD;
    const float scale = (s == 0) ? 0.125f : 1.0f;
#pragma unroll
    for (int t = 0; t < 16; t++) {
        int l = t * 256 + tid;
        int n = l >> 6, d = l & 63;
        dst[(size_t)(n0 + n) * DHEAD + d] = Ss[d][n] * scale;
    }
}

// ---------------------------------------------------------------------------
// Kernel 2: flash attention on tensor cores (mma.sync tf32, fp32 softmax).
// grid (NTOK/64, NHEAD, BATCH), 128 threads = 4 warps, 16 query rows/warp.
// Smem pitches: K/P = 68 (pattern bank 4g+tig conflict-free),
//               V   = 72 (pattern bank 8tig+g conflict-free).
// ---------------------------------------------------------------------------
#define PK 68
#define PV 72
#define ATTN_SMEM_FLOATS (64*PK + 64*PV + 64*PK)   // Ks, Vs, Ps

__global__ __launch_bounds__(128) void attn_kernel() {
    extern __shared__ float sm[];
    float* Ks = sm;                       // [64][PK]
    float* Vs = sm + 64 * PK;             // [64][PV]
    float* Ps = sm + 64 * PK + 64 * PV;   // [64][PK]

    const int b = blockIdx.z, h = blockIdx.y;
    const int n0 = blockIdx.x * 64;
    const int bh = b * NHEAD + h;
    const float* q = g_q + (size_t)bh * NTOK * DHEAD;
    const float* k = g_k + (size_t)bh * NTOK * DHEAD;
    const float* v = g_v + (size_t)bh * NTOK * DHEAD;

    const int tid  = threadIdx.x;
    const int warp = tid >> 5, lane = tid & 31;
    const int g    = lane >> 2, tig = lane & 3;
    const int rb   = warp * 16;           // warp's query-row base within tile

    // Q fragments resident in registers (tf32), 16 rows x 64 cols per warp
    uint32_t qa[8][4];
#pragma unroll
    for (int kk = 0; kk < 8; kk++) {
        const int c0 = kk * 8 + tig;
        qa[kk][0] = f2tf32(q[(size_t)(n0 + rb + g)     * DHEAD + c0]);
        qa[kk][1] = f2tf32(q[(size_t)(n0 + rb + g + 8) * DHEAD + c0]);
        qa[kk][2] = f2tf32(q[(size_t)(n0 + rb + g)     * DHEAD + c0 + 4]);
        qa[kk][3] = f2tf32(q[(size_t)(n0 + rb + g + 8) * DHEAD + c0 + 4]);
    }

    float o[8][4] = {};
    float m0 = -1e30f, m1 = -1e30f, l0 = 0.0f, l1 = 0.0f;

    for (int j0 = 0; j0 < NTOK; j0 += 64) {
        __syncthreads();   // prior-iteration reads of Ks/Vs/Ps complete
        // cooperative K/V tile load (float4, converted to tf32 in smem)
#pragma unroll
        for (int t = 0; t < 8; t++) {
            int l = t * 128 + tid;
            int r = l >> 4, c = (l & 15) * 4;
            float4 kv = *(const float4*)(k + (size_t)(j0 + r) * DHEAD + c);
            float4 kt = { f2tf32f(kv.x), f2tf32f(kv.y), f2tf32f(kv.z), f2tf32f(kv.w) };
            *(float4*)(Ks + r * PK + c) = kt;
            float4 vv = *(const float4*)(v + (size_t)(j0 + r) * DHEAD + c);
            float4 vt = { f2tf32f(vv.x), f2tf32f(vv.y), f2tf32f(vv.z), f2tf32f(vv.w) };
            *(float4*)(Vs + r * PV + c) = vt;
        }
        __syncthreads();

        // S = Q @ K^T (scale folded into Q)
        float sc[8][4] = {};
#pragma unroll
        for (int nt = 0; nt < 8; nt++) {
            const float* krow = Ks + (nt * 8 + g) * PK;
#pragma unroll
            for (int kk = 0; kk < 8; kk++) {
                uint32_t b0 = __float_as_uint(krow[kk * 8 + tig]);
                uint32_t b1 = __float_as_uint(krow[kk * 8 + tig + 4]);
                mma_tf32(sc[nt], qa[kk], b0, b1);
            }
        }

        // online softmax: rows (rb+g) -> m0/l0, (rb+g+8) -> m1/l1
        float mx0 = m0, mx1 = m1;
#pragma unroll
        for (int nt = 0; nt < 8; nt++) {
            mx0 = fmaxf(mx0, fmaxf(sc[nt][0], sc[nt][1]));
            mx1 = fmaxf(mx1, fmaxf(sc[nt][2], sc[nt][3]));
        }
        mx0 = fmaxf(mx0, __shfl_xor_sync(0xffffffffu, mx0, 1));
        mx0 = fmaxf(mx0, __shfl_xor_sync(0xffffffffu, mx0, 2));
        mx1 = fmaxf(mx1, __shfl_xor_sync(0xffffffffu, mx1, 1));
        mx1 = fmaxf(mx1, __shfl_xor_sync(0xffffffffu, mx1, 2));
        const float a0 = __expf(m0 - mx0);
        const float a1 = __expf(m1 - mx1);
        float s0 = 0.0f, s1 = 0.0f;
#pragma unroll
        for (int nt = 0; nt < 8; nt++) {
            sc[nt][0] = __expf(sc[nt][0] - mx0);
            sc[nt][1] = __expf(sc[nt][1] - mx0);
            sc[nt][2] = __expf(sc[nt][2] - mx1);
            sc[nt][3] = __expf(sc[nt][3] - mx1);
            s0 += sc[nt][0] + sc[nt][1];
            s1 += sc[nt][2] + sc[nt][3];
        }
        s0 += __shfl_xor_sync(0xffffffffu, s0, 1);
        s0 += __shfl_xor_sync(0xffffffffu, s0, 2);
        s1 += __shfl_xor_sync(0xffffffffu, s1, 1);
        s1 += __shfl_xor_sync(0xffffffffu, s1, 2);
        m0 = mx0; m1 = mx1;
        l0 = l0 * a0 + s0;
        l1 = l1 * a1 + s1;
#pragma unroll
        for (int dt = 0; dt < 8; dt++) {
            o[dt][0] *= a0; o[dt][1] *= a0;
            o[dt][2] *= a1; o[dt][3] *= a1;
        }

        // stage P (tf32) to smem in [row][col] layout
#pragma unroll
        for (int nt = 0; nt < 8; nt++) {
            float2 p01 = { f2tf32f(sc[nt][0]), f2tf32f(sc[nt][1]) };
            float2 p23 = { f2tf32f(sc[nt][2]), f2tf32f(sc[nt][3]) };
            *(float2*)(Ps + (rb + g)     * PK + nt * 8 + tig * 2) = p01;
            *(float2*)(Ps + (rb + g + 8) * PK + nt * 8 + tig * 2) = p23;
        }
        __syncthreads();

        // O += P @ V
#pragma unroll
        for (int kk = 0; kk < 8; kk++) {
            uint32_t pa[4];
            pa[0] = __float_as_uint(Ps[(rb + g)     * PK + kk * 8 + tig]);
            pa[1] = __float_as_uint(Ps[(rb + g + 8) * PK + kk * 8 + tig]);
            pa[2] = __float_as_uint(Ps[(rb + g)     * PK + kk * 8 + tig + 4]);
            pa[3] = __float_as_uint(Ps[(rb + g + 8) * PK + kk * 8 + tig + 4]);
#pragma unroll
            for (int dt = 0; dt < 8; dt++) {
                uint32_t b0 = __float_as_uint(Vs[(kk * 8 + tig)     * PV + dt * 8 + g]);
                uint32_t b1 = __float_as_uint(Vs[(kk * 8 + tig + 4) * PV + dt * 8 + g]);
                mma_tf32(o[dt], pa, b0, b1);
            }
        }
    }

    // normalize and stage transposed output Od[d][n] (pitch 65, reuse smem)
    const float inv0 = 1.0f / l0, inv1 = 1.0f / l1;
    __syncthreads();
    float* Od = sm;   // needs 64*65 = 4160 floats
#pragma unroll
    for (int dt = 0; dt < 8; dt++) {
        int d = dt * 8 + 2 * tig;
        Od[d * 65 + rb + g]           = o[dt][0] * inv0;
        Od[(d + 1) * 65 + rb + g]     = o[dt][1] * inv0;
        Od[d * 65 + rb + g + 8]       = o[dt][2] * inv1;
        Od[(d + 1) * 65 + rb + g + 8] = o[dt][3] * inv1;
    }
    __syncthreads();
    float* dst = g_o + (size_t)(bh * DHEAD) * NTOK;
#pragma unroll
    for (int t = 0; t < 32; t++) {
        int idx = t * 128 + tid;
        int d = idx >> 6, n = idx & 63;
        dst[(size_t)d * NTOK + n0 + n] = Od[d * 65 + n];
    }
}

// ---------------------------------------------------------------------------
// Kernel 3: output projection. out[b,c,n] = sum_i Wo[c,i]*g_o[b,i,n] + bias[c]
// ---------------------------------------------------------------------------
__global__ __launch_bounds__(256) void proj_kernel(const float* __restrict__ wo,
                                                   const float* __restrict__ bias,
                                                   float* __restrict__ out) {
    __shared__ float Ws[16][65];
    __shared__ float Xs[16][65];
    __shared__ float Ss[64][65];

    const int b  = blockIdx.z;
    const int c0 = blockIdx.y * 64;
    const int n0 = blockIdx.x * 64;
    const int tid = threadIdx.x;
    const int tx = tid & 15, ty = tid >> 4;

    const float* gb = g_o + (size_t)b * INNER * NTOK;
    float acc[4][4] = {};

    for (int kt = 0; kt < INNER; kt += 16) {
#pragma unroll
        for (int t = 0; t < 4; t++) {
            int l = t * 256 + tid;
            int o = l >> 4, kk = l & 15;
            Ws[kk][o] = wo[(c0 + o) * INNER + kt + kk];
        }
#pragma unroll
        for (int t = 0; t < 4; t++) {
            int l = t * 256 + tid;
            int kk = l >> 6, n = l & 63;
            Xs[kk][n] = gb[(size_t)(kt + kk) * NTOK + n0 + n];
        }
        __syncthreads();
#pragma unroll
        for (int kk = 0; kk < 16; kk++) {
            float a[4], bb[4];
#pragma unroll
            for (int i = 0; i < 4; i++) a[i]  = Ws[kk][ty * 4 + i];
#pragma unroll
            for (int j = 0; j < 4; j++) bb[j] = Xs[kk][tx + 16 * j];
#pragma unroll
            for (int i = 0; i < 4; i++)
#pragma unroll
                for (int j = 0; j < 4; j++)
                    acc[i][j] = fmaf(a[i], bb[j], acc[i][j]);
        }
        __syncthreads();
    }

#pragma unroll
    for (int i = 0; i < 4; i++)
#pragma unroll
        for (int j = 0; j < 4; j++)
            Ss[ty * 4 + i][tx + 16 * j] = acc[i][j];
    __syncthreads();

#pragma unroll
    for (int t = 0; t < 16; t++) {
        int l = t * 256 + tid;
        int r = l >> 6, n = l & 63;
        out[(size_t)(b * CH + c0 + r) * NTOK + n0 + n] = Ss[r][n] + bias[c0 + r];
    }
}

// ---------------------------------------------------------------------------
extern "C" void kernel_launch(void* const* d_in, const int* in_sizes, int n_in,
                              void* d_out, int out_size) {
    const float* x    = nullptr;
    const float* wqkv = nullptr;
    const float* wout = nullptr;
    const float* bout = nullptr;
    for (int i = 0; i < n_in; i++) {
        int sz = in_sizes[i];
        const float* p = (const float*)d_in[i];
        if      (sz == BATCH * CH * NTOK) x    = p;
        else if (sz == 3 * INNER * CH)    wqkv = p;
        else if (sz == CH * INNER)        wout = p;
        else if (sz == CH)                bout = p;
    }
    float* out = (float*)d_out;

    qkv_kernel<<<dim3(NTOK / 64, (3 * INNER) / 64, BATCH), 256>>>(x, wqkv);

    const int attn_smem = ATTN_SMEM_FLOATS * (int)sizeof(float);  // 53,248 B
    cudaFuncSetAttribute(attn_kernel,
                         cudaFuncAttributeMaxDynamicSharedMemorySize, attn_smem);
    attn_kernel<<<dim3(NTOK / 64, NHEAD, BATCH), 128, attn_smem>>>();

    proj_kernel<<<dim3(NTOK / 64, CH / 64, BATCH), 256>>>(wout, bout, out);
}

// round 6
// speedup vs baseline: 3.2995x; 1.3841x over previous
#include <cuda_runtime.h>
#include <cuda_bf16.h>
#include <cstdint>

#define BATCH 2
#define CH    256
#define NTOK  4096
#define NHEAD 8
#define DHEAD 64
#define INNER 512

// Scratch (no cudaMalloc allowed): q/k/v in [b][h][n][d], attn out in [b][i=h*64+d][n]
__device__ float g_q[BATCH*NHEAD*NTOK*DHEAD];
__device__ float g_k[BATCH*NHEAD*NTOK*DHEAD];
__device__ float g_v[BATCH*NHEAD*NTOK*DHEAD];
__device__ float g_o[BATCH*INNER*NTOK];

// ---------------------------------------------------------------------------
// tf32 helpers
// ---------------------------------------------------------------------------
__device__ __forceinline__ uint32_t f2tf32(float x) {
    uint32_t u;
    asm("cvt.rna.tf32.f32 %0, %1;" : "=r"(u) : "f"(x));
    return u;
}
__device__ __forceinline__ float f2tf32f(float x) {
    return __uint_as_float(f2tf32(x));
}
__device__ __forceinline__ void mma_tf32(float* c, const uint32_t* a,
                                         uint32_t b0, uint32_t b1) {
    asm volatile(
        "mma.sync.aligned.m16n8k8.row.col.f32.tf32.tf32.f32 "
        "{%0,%1,%2,%3}, {%4,%5,%6,%7}, {%8,%9}, {%0,%1,%2,%3};"
        : "+f"(c[0]), "+f"(c[1]), "+f"(c[2]), "+f"(c[3])
        : "r"(a[0]), "r"(a[1]), "r"(a[2]), "r"(a[3]), "r"(b0), "r"(b1));
}

// ---------------------------------------------------------------------------
// Kernel 1: QKV projection on tensor cores.
// Y[b,o,n] = sum_c W[o,c] * x[b,c,n].  Tile 64(o) x 64(n), BK=16, 4 warps.
// Each warp: 16 o-rows x 64 n. Q pre-scaled by 0.125 at write.
// ---------------------------------------------------------------------------
__global__ __launch_bounds__(128) void qkv_tc(const float* __restrict__ x,
                                              const float* __restrict__ w) {
    __shared__ float As[64][20];   // [o][k], pitch 20: frag loads conflict-free
    __shared__ float Bs[16][72];   // [k][n], pitch 72
    __shared__ float Cs[64][72];   // staging [n][d]

    const int b  = blockIdx.z;
    const int o0 = blockIdx.y * 64;
    const int n0 = blockIdx.x * 64;
    const int tid  = threadIdx.x;
    const int warp = tid >> 5, lane = tid & 31;
    const int g = lane >> 2, tig = lane & 3;
    const int mw = warp * 16;

    const float* xb = x + (size_t)b * CH * NTOK;
    float sc[8][4] = {};

    for (int kt = 0; kt < CH; kt += 16) {
#pragma unroll
        for (int t = 0; t < 2; t++) {
            int l = t * 128 + tid;
            int o = l >> 2, k4 = (l & 3) * 4;
            float4 a = *(const float4*)(w + (size_t)(o0 + o) * CH + kt + k4);
            *(float4*)(&As[o][k4]) = a;
        }
#pragma unroll
        for (int t = 0; t < 2; t++) {
            int l = t * 128 + tid;
            int kk = l >> 4, n4 = (l & 15) * 4;
            float4 v = *(const float4*)(xb + (size_t)(kt + kk) * NTOK + n0 + n4);
            float4 vt = { f2tf32f(v.x), f2tf32f(v.y), f2tf32f(v.z), f2tf32f(v.w) };
            *(float4*)(&Bs[kk][n4]) = vt;
        }
        __syncthreads();
#pragma unroll
        for (int kk = 0; kk < 2; kk++) {
            uint32_t a[4];
            a[0] = f2tf32(As[mw + g]    [kk * 8 + tig]);
            a[1] = f2tf32(As[mw + g + 8][kk * 8 + tig]);
            a[2] = f2tf32(As[mw + g]    [kk * 8 + tig + 4]);
            a[3] = f2tf32(As[mw + g + 8][kk * 8 + tig + 4]);
#pragma unroll
            for (int nt = 0; nt < 8; nt++) {
                uint32_t b0 = __float_as_uint(Bs[kk * 8 + tig]    [nt * 8 + g]);
                uint32_t b1 = __float_as_uint(Bs[kk * 8 + tig + 4][nt * 8 + g]);
                mma_tf32(sc[nt], a, b0, b1);
            }
        }
        __syncthreads();
    }

    // stage C transposed: Cs[n][d]  (d = o within 64-row tile)
#pragma unroll
    for (int nt = 0; nt < 8; nt++) {
        Cs[nt * 8 + 2 * tig]    [mw + g]     = sc[nt][0];
        Cs[nt * 8 + 2 * tig + 1][mw + g]     = sc[nt][1];
        Cs[nt * 8 + 2 * tig]    [mw + g + 8] = sc[nt][2];
        Cs[nt * 8 + 2 * tig + 1][mw + g + 8] = sc[nt][3];
    }
    __syncthreads();

    const int s = o0 >> 9;           // 0=q 1=k 2=v  (tile never straddles)
    const int h = (o0 >> 6) & 7;
    float* dst = (s == 0 ? g_q : (s == 1 ? g_k : g_v)) +
                 (size_t)(b * NHEAD + h) * NTOK * DHEAD;
    const float scale = (s == 0) ? 0.125f : 1.0f;
#pragma unroll
    for (int it = 0; it < 8; it++) {
        int l = it * 128 + tid;
        int n = l >> 4, d4 = (l & 15) * 4;
        float4 c = *(const float4*)(&Cs[n][d4]);
        c.x *= scale; c.y *= scale; c.z *= scale; c.w *= scale;
        *(float4*)(dst + (size_t)(n0 + n) * DHEAD + d4) = c;
    }
}

// ---------------------------------------------------------------------------
// Kernel 2: flash attention, tf32 mma, fp32 softmax, shfl-based P relayout.
// grid (64, 8, 2), 128 threads = 4 warps, 16 q-rows/warp.
// smem = K[64][68] + V[64][72] = 35.8KB -> 6 blocks/SM.
// ---------------------------------------------------------------------------
#define PK 68
#define PV 72

__global__ __launch_bounds__(128) void attn_kernel() {
    __shared__ float sm[64 * PK + 64 * PV];
    float* Ks = sm;
    float* Vs = sm + 64 * PK;

    const int b = blockIdx.z, h = blockIdx.y;
    const int n0 = blockIdx.x * 64;
    const int bh = b * NHEAD + h;
    const float* q = g_q + (size_t)bh * NTOK * DHEAD;
    const float* k = g_k + (size_t)bh * NTOK * DHEAD;
    const float* v = g_v + (size_t)bh * NTOK * DHEAD;

    const int tid  = threadIdx.x;
    const int warp = tid >> 5, lane = tid & 31;
    const int g    = lane >> 2, tig = lane & 3;
    const int rb   = warp * 16;

    // Q fragments resident in registers (tf32), 16 rows x 64 cols per warp
    uint32_t qa[8][4];
#pragma unroll
    for (int kk = 0; kk < 8; kk++) {
        const int c0 = kk * 8 + tig;
        qa[kk][0] = f2tf32(q[(size_t)(n0 + rb + g)     * DHEAD + c0]);
        qa[kk][1] = f2tf32(q[(size_t)(n0 + rb + g + 8) * DHEAD + c0]);
        qa[kk][2] = f2tf32(q[(size_t)(n0 + rb + g)     * DHEAD + c0 + 4]);
        qa[kk][3] = f2tf32(q[(size_t)(n0 + rb + g + 8) * DHEAD + c0 + 4]);
    }

    float o[8][4] = {};
    float m0 = -1e30f, m1 = -1e30f, l0 = 0.0f, l1 = 0.0f;

    for (int j0 = 0; j0 < NTOK; j0 += 64) {
        __syncthreads();   // prior-iteration reads of Ks/Vs complete
#pragma unroll
        for (int t = 0; t < 8; t++) {
            int l = t * 128 + tid;
            int r = l >> 4, c = (l & 15) * 4;
            float4 kv = *(const float4*)(k + (size_t)(j0 + r) * DHEAD + c);
            float4 kt = { f2tf32f(kv.x), f2tf32f(kv.y), f2tf32f(kv.z), f2tf32f(kv.w) };
            *(float4*)(Ks + r * PK + c) = kt;
            float4 vv = *(const float4*)(v + (size_t)(j0 + r) * DHEAD + c);
            float4 vt = { f2tf32f(vv.x), f2tf32f(vv.y), f2tf32f(vv.z), f2tf32f(vv.w) };
            *(float4*)(Vs + r * PV + c) = vt;
        }
        __syncthreads();

        // S = Q @ K^T (scale folded into Q)
        float sc[8][4] = {};
#pragma unroll
        for (int nt = 0; nt < 8; nt++) {
            const float* krow = Ks + (nt * 8 + g) * PK;
#pragma unroll
            for (int kk = 0; kk < 8; kk++) {
                uint32_t b0 = __float_as_uint(krow[kk * 8 + tig]);
                uint32_t b1 = __float_as_uint(krow[kk * 8 + tig + 4]);
                mma_tf32(sc[nt], qa[kk], b0, b1);
            }
        }

        // online softmax: rows (rb+g) -> m0/l0, (rb+g+8) -> m1/l1
        float mx0 = m0, mx1 = m1;
#pragma unroll
        for (int nt = 0; nt < 8; nt++) {
            mx0 = fmaxf(mx0, fmaxf(sc[nt][0], sc[nt][1]));
            mx1 = fmaxf(mx1, fmaxf(sc[nt][2], sc[nt][3]));
        }
        mx0 = fmaxf(mx0, __shfl_xor_sync(0xffffffffu, mx0, 1));
        mx0 = fmaxf(mx0, __shfl_xor_sync(0xffffffffu, mx0, 2));
        mx1 = fmaxf(mx1, __shfl_xor_sync(0xffffffffu, mx1, 1));
        mx1 = fmaxf(mx1, __shfl_xor_sync(0xffffffffu, mx1, 2));
        const float a0 = __expf(m0 - mx0);
        const float a1 = __expf(m1 - mx1);
        float s0 = 0.0f, s1 = 0.0f;
#pragma unroll
        for (int nt = 0; nt < 8; nt++) {
            sc[nt][0] = __expf(sc[nt][0] - mx0);
            sc[nt][1] = __expf(sc[nt][1] - mx0);
            sc[nt][2] = __expf(sc[nt][2] - mx1);
            sc[nt][3] = __expf(sc[nt][3] - mx1);
            s0 += sc[nt][0] + sc[nt][1];
            s1 += sc[nt][2] + sc[nt][3];
        }
        s0 += __shfl_xor_sync(0xffffffffu, s0, 1);
        s0 += __shfl_xor_sync(0xffffffffu, s0, 2);
        s1 += __shfl_xor_sync(0xffffffffu, s1, 1);
        s1 += __shfl_xor_sync(0xffffffffu, s1, 2);
        m0 = mx0; m1 = mx1;
        l0 = l0 * a0 + s0;
        l1 = l1 * a1 + s1;
#pragma unroll
        for (int dt = 0; dt < 8; dt++) {
            o[dt][0] *= a0; o[dt][1] *= a0;
            o[dt][2] *= a1; o[dt][3] *= a1;
        }

        // O += P @ V.  Build P A-fragments from C-fragments via shuffles:
        // element P[g][c] lives in lane (g, (c&7)>>1), reg (c&1) of sc[c>>3].
        const bool odd = (tig & 1);
#pragma unroll
        for (int kk = 0; kk < 8; kk++) {
            const int srcA = (g << 2) | (tig >> 1);   // cols kk*8+tig
            const int srcB = srcA + 2;                // cols kk*8+tig+4
            float e0 = __shfl_sync(0xffffffffu, sc[kk][0], srcA);
            float e1 = __shfl_sync(0xffffffffu, sc[kk][1], srcA);
            float e2 = __shfl_sync(0xffffffffu, sc[kk][2], srcA);
            float e3 = __shfl_sync(0xffffffffu, sc[kk][3], srcA);
            float f0 = __shfl_sync(0xffffffffu, sc[kk][0], srcB);
            float f1 = __shfl_sync(0xffffffffu, sc[kk][1], srcB);
            float f2 = __shfl_sync(0xffffffffu, sc[kk][2], srcB);
            float f3 = __shfl_sync(0xffffffffu, sc[kk][3], srcB);
            uint32_t pa[4];
            pa[0] = f2tf32(odd ? e1 : e0);   // P[g]   [kk*8+tig]
            pa[1] = f2tf32(odd ? e3 : e2);   // P[g+8] [kk*8+tig]
            pa[2] = f2tf32(odd ? f1 : f0);   // P[g]   [kk*8+tig+4]
            pa[3] = f2tf32(odd ? f3 : f2);   // P[g+8] [kk*8+tig+4]
#pragma unroll
            for (int dt = 0; dt < 8; dt++) {
                uint32_t b0 = __float_as_uint(Vs[(kk * 8 + tig)     * PV + dt * 8 + g]);
                uint32_t b1 = __float_as_uint(Vs[(kk * 8 + tig + 4) * PV + dt * 8 + g]);
                mma_tf32(o[dt], pa, b0, b1);
            }
        }
    }

    // normalize and stage transposed output Od[d][n] (pitch 65, reuse smem)
    const float inv0 = 1.0f / l0, inv1 = 1.0f / l1;
    __syncthreads();
    float* Od = sm;   // 64*65 = 4160 floats, fits in 8960
#pragma unroll
    for (int dt = 0; dt < 8; dt++) {
        int d = dt * 8 + 2 * tig;
        Od[d * 65 + rb + g]           = o[dt][0] * inv0;
        Od[(d + 1) * 65 + rb + g]     = o[dt][1] * inv0;
        Od[d * 65 + rb + g + 8]       = o[dt][2] * inv1;
        Od[(d + 1) * 65 + rb + g + 8] = o[dt][3] * inv1;
    }
    __syncthreads();
    float* dst = g_o + (size_t)(bh * DHEAD) * NTOK;
#pragma unroll
    for (int t = 0; t < 32; t++) {
        int idx = t * 128 + tid;
        int d = idx >> 6, n = idx & 63;
        dst[(size_t)d * NTOK + n0 + n] = Od[d * 65 + n];
    }
}

// ---------------------------------------------------------------------------
// Kernel 3: output projection on tensor cores.
// out[b,c,n] = sum_i Wo[c,i]*g_o[b,i,n] + bias[c].  Tile 64x64, BK=16.
// ---------------------------------------------------------------------------
__global__ __launch_bounds__(128) void proj_tc(const float* __restrict__ wo,
                                               const float* __restrict__ bias,
                                               float* __restrict__ out) {
    __shared__ float As[64][20];
    __shared__ float Bs[16][72];
    __shared__ float Cs[64][72];   // staging [c][n]

    const int b  = blockIdx.z;
    const int c0 = blockIdx.y * 64;
    const int n0 = blockIdx.x * 64;
    const int tid  = threadIdx.x;
    const int warp = tid >> 5, lane = tid & 31;
    const int g = lane >> 2, tig = lane & 3;
    const int mw = warp * 16;

    const float* gb = g_o + (size_t)b * INNER * NTOK;
    float sc[8][4] = {};

    for (int kt = 0; kt < INNER; kt += 16) {
#pragma unroll
        for (int t = 0; t < 2; t++) {
            int l = t * 128 + tid;
            int o = l >> 2, k4 = (l & 3) * 4;
            float4 a = *(const float4*)(wo + (size_t)(c0 + o) * INNER + kt + k4);
            *(float4*)(&As[o][k4]) = a;
        }
#pragma unroll
        for (int t = 0; t < 2; t++) {
            int l = t * 128 + tid;
            int kk = l >> 4, n4 = (l & 15) * 4;
            float4 v = *(const float4*)(gb + (size_t)(kt + kk) * NTOK + n0 + n4);
            float4 vt = { f2tf32f(v.x), f2tf32f(v.y), f2tf32f(v.z), f2tf32f(v.w) };
            *(float4*)(&Bs[kk][n4]) = vt;
        }
        __syncthreads();
#pragma unroll
        for (int kk = 0; kk < 2; kk++) {
            uint32_t a[4];
            a[0] = f2tf32(As[mw + g]    [kk * 8 + tig]);
            a[1] = f2tf32(As[mw + g + 8][kk * 8 + tig]);
            a[2] = f2tf32(As[mw + g]    [kk * 8 + tig + 4]);
            a[3] = f2tf32(As[mw + g + 8][kk * 8 + tig + 4]);
#pragma unroll
            for (int nt = 0; nt < 8; nt++) {
                uint32_t b0 = __float_as_uint(Bs[kk * 8 + tig]    [nt * 8 + g]);
                uint32_t b1 = __float_as_uint(Bs[kk * 8 + tig + 4][nt * 8 + g]);
                mma_tf32(sc[nt], a, b0, b1);
            }
        }
        __syncthreads();
    }

    // stage [c][n]
#pragma unroll
    for (int nt = 0; nt < 8; nt++) {
        *(float2*)(&Cs[mw + g]    [nt * 8 + 2 * tig]) = make_float2(sc[nt][0], sc[nt][1]);
        *(float2*)(&Cs[mw + g + 8][nt * 8 + 2 * tig]) = make_float2(sc[nt][2], sc[nt][3]);
    }
    __syncthreads();

#pragma unroll
    for (int it = 0; it < 8; it++) {
        int l = it * 128 + tid;
        int c = l >> 4, n4 = (l & 15) * 4;
        float4 r = *(const float4*)(&Cs[c][n4]);
        float bv = bias[c0 + c];
        r.x += bv; r.y += bv; r.z += bv; r.w += bv;
        *(float4*)(out + (size_t)(b * CH + c0 + c) * NTOK + n0 + n4) = r;
    }
}

// ---------------------------------------------------------------------------
extern "C" void kernel_launch(void* const* d_in, const int* in_sizes, int n_in,
                              void* d_out, int out_size) {
    const float* x    = nullptr;
    const float* wqkv = nullptr;
    const float* wout = nullptr;
    const float* bout = nullptr;
    for (int i = 0; i < n_in; i++) {
        int sz = in_sizes[i];
        const float* p = (const float*)d_in[i];
        if      (sz == BATCH * CH * NTOK) x    = p;
        else if (sz == 3 * INNER * CH)    wqkv = p;
        else if (sz == CH * INNER)        wout = p;
        else if (sz == CH)                bout = p;
    }
    float* out = (float*)d_out;

    qkv_tc<<<dim3(NTOK / 64, (3 * INNER) / 64, BATCH), 128>>>(x, wqkv);
    attn_kernel<<<dim3(NTOK / 64, NHEAD, BATCH), 128>>>();
    proj_tc<<<dim3(NTOK / 64, CH / 64, BATCH), 128>>>(wout, bout, out);
}